// round 8
// baseline (speedup 1.0000x reference)
#include <cuda_runtime.h>
#include <cuda_fp16.h>
#include <cstdint>
#include <math.h>

// ---------------------------------------------------------------------------
#define DM     512
#define NSEQ   2048
#define CH     8
#define BATCH  4
#define BCN    (BATCH*CH)            // 32 attention batches
#define MROWS  (BATCH*NSEQ*CH)       // 65536 projection rows
#define OUT_OFF_ATTN ((size_t)BATCH*NSEQ*CH*DM)
#define QKV_SPAN ((size_t)BCN*NSEQ*DM)

// Scratch (device globals — allocation-free per harness rules)
__device__ __half g_qkv[3*QKV_SPAN];              // qp | kp | vp, each [z][n][d]
__device__ __half g_ctx[QKV_SPAN];                // [z][n][d]
__device__ __half g_sc [(size_t)BCN*NSEQ*NSEQ];   // fp16 scores / normalized attn
__device__ __half g_wt [4*(size_t)DM*DM];         // W^T as [out][in], fp16

struct P3 { const float* a[3]; const float* b[3]; };
struct W4 { const float* w[4]; };

// ---------------------------------------------------------------------------
__device__ __forceinline__ uint32_t smem_u32(const void* p) {
    uint32_t a;
    asm("{ .reg .u64 t; cvta.to.shared.u64 t, %1; cvt.u32.u64 %0, t; }"
        : "=r"(a) : "l"(p));
    return a;
}
__device__ __forceinline__ void cpa16(uint32_t d, const void* s) {
    asm volatile("cp.async.cg.shared.global [%0], [%1], 16;" :: "r"(d), "l"(s));
}
__device__ __forceinline__ void cpcommit() {
    asm volatile("cp.async.commit_group;" ::: "memory");
}
template<int N> __device__ __forceinline__ void cpwait() {
    asm volatile("cp.async.wait_group %0;" :: "n"(N) : "memory");
}
#define LDSM4(r, a)                                                           \
    asm volatile("ldmatrix.sync.aligned.m8n8.x4.shared.b16 {%0,%1,%2,%3}, [%4];" \
        : "=r"((r)[0]), "=r"((r)[1]), "=r"((r)[2]), "=r"((r)[3]) : "r"(a))
#define LDSM4T(r, a)                                                          \
    asm volatile("ldmatrix.sync.aligned.m8n8.x4.trans.shared.b16 {%0,%1,%2,%3}, [%4];" \
        : "=r"((r)[0]), "=r"((r)[1]), "=r"((r)[2]), "=r"((r)[3]) : "r"(a))

__device__ __forceinline__ void mma16816(float* c, const uint32_t* a,
                                         uint32_t b0, uint32_t b1) {
    asm volatile(
        "mma.sync.aligned.m16n8k16.row.col.f32.f16.f16.f32 "
        "{%0,%1,%2,%3}, {%4,%5,%6,%7}, {%8,%9}, {%0,%1,%2,%3};"
        : "+f"(c[0]), "+f"(c[1]), "+f"(c[2]), "+f"(c[3])
        : "r"(a[0]), "r"(a[1]), "r"(a[2]), "r"(a[3]), "r"(b0), "r"(b1));
}

// ---------------------------------------------------------------------------
// Block tile 128x256xKC(=64), 512 threads = 16 warps of 64x32, 2-stage pipe.
// MODE 0: projections q/k/v (z picks input/W/bias/out), f32 A, half out
// MODE 2: scores      C = scale * Q @ K^T, half in, HALF out (to g_sc)
// MODE 3: AV          C = attnH @ V, A half, V loaded [m][d] w/ ldmatrix.trans
// MODE 4: out proj    C = relu(ctx(h)@Wo^T + b), remap (b,c,n)->(b,n,c), f32
// ---------------------------------------------------------------------------
#define KC     64
#define LDA_S  72          // halves: 64 + 8 pad
#define LDB_T  264         // halves for BTR tiles (256 + 8 pad)
#define ABUF   (128*LDA_S)             // 9216 halves
#define BBUF   (256*LDA_S)             // 18432 halves (>= 64*LDB_T = 16896)
#define STAGE  (ABUF + BBUF)
#define NTHR   512

template<int MODE>
__global__ __launch_bounds__(NTHR) void gemm_mma(
    const void* __restrict__ Ag, const __half* __restrict__ Bg,
    const float* __restrict__ bias, void* __restrict__ Cg, P3 pp)
{
    extern __shared__ __half sh[];
    constexpr int  K     = (MODE == 3) ? NSEQ : DM;
    constexpr int  ITERS = K / KC;
    constexpr bool ACVT  = (MODE == 0);
    constexpr bool BTR   = (MODE == 3);
    constexpr int  LDAE  = (MODE == 3) ? NSEQ : DM;

    const int tid = threadIdx.x, lane = tid & 31, wid = tid >> 5;
    const int wr = wid >> 3, wc = wid & 7;     // 2 x 8 warps -> 64x32 tiles
    const int z = blockIdx.z;
    const int rowBase = blockIdx.y * 128, colBase = blockIdx.x * 256;

    const float* Af = ACVT ? pp.a[z] : nullptr;
    const float* bias_p = ACVT ? pp.b[z] : bias;
    const __half* Ah = (const __half*)Ag +
        (MODE == 2 ? (size_t)z*NSEQ*DM : MODE == 3 ? (size_t)z*NSEQ*NSEQ : 0);
    const __half* Bp = Bg +
        (MODE == 0 ? (size_t)z*DM*DM :
         (MODE == 2 || MODE == 3) ? (size_t)z*NSEQ*DM : 0);

    const uint32_t sbase = smem_u32(sh);

    float acc[4][4][4];
    #pragma unroll
    for (int i = 0; i < 4; i++)
        #pragma unroll
        for (int j = 0; j < 4; j++)
            #pragma unroll
            for (int q = 0; q < 4; q++) acc[i][j][q] = 0.f;

    // ---- loaders (512 threads) ----
    const int avr = tid & 127;      // CVT: row
    const int avh = tid >> 7;       // CVT: 16-col chunk (0..3)
    float4 fA[4];

    auto loadA_cvt = [&](int kb) {
        const float* s = Af + (size_t)(rowBase + avr) * LDAE + kb + avh * 16;
        #pragma unroll
        for (int u = 0; u < 4; u++) fA[u] = *(const float4*)(s + u*4);
    };
    auto stsA_cvt = [&](int buf) {
        __half hv[16];
        #pragma unroll
        for (int u = 0; u < 4; u++) {
            hv[u*4+0] = __float2half_rn(fA[u].x);
            hv[u*4+1] = __float2half_rn(fA[u].y);
            hv[u*4+2] = __float2half_rn(fA[u].z);
            hv[u*4+3] = __float2half_rn(fA[u].w);
        }
        __half* d = sh + buf*STAGE + avr*LDA_S + avh*16;
        *(uint4*)d       = ((uint4*)hv)[0];
        *((uint4*)d + 1) = ((uint4*)hv)[1];
    };
    auto issueA_async = [&](int buf, int kb) {
        #pragma unroll
        for (int i = 0; i < 2; i++) {
            int idx = tid + i*NTHR;
            int h = idx & 7, r = idx >> 3;
            cpa16(sbase + (uint32_t)(buf*STAGE + r*LDA_S + h*8)*2,
                  Ah + (size_t)(rowBase + r)*LDAE + kb + h*8);
        }
    };
    auto issueB = [&](int buf, int kb) {
        if constexpr (BTR) {
            #pragma unroll
            for (int i = 0; i < 4; i++) {
                int idx = tid + i*NTHR;
                int r = idx >> 5, h = idx & 31;
                cpa16(sbase + (uint32_t)(buf*STAGE + ABUF + r*LDB_T + h*8)*2,
                      Bp + (size_t)(kb + r)*DM + colBase + h*8);
            }
        } else {
            #pragma unroll
            for (int i = 0; i < 4; i++) {
                int idx = tid + i*NTHR;
                int h = idx & 7, r = idx >> 3;
                cpa16(sbase + (uint32_t)(buf*STAGE + ABUF + r*LDA_S + h*8)*2,
                      Bp + (size_t)(colBase + r)*DM + kb + h*8);
            }
        }
    };

    // ---- prologue ----
    if constexpr (ACVT) { loadA_cvt(0); stsA_cvt(0); }
    else issueA_async(0, 0);
    issueB(0, 0);
    cpcommit();

    // ---- main loop (2-stage) ----
    for (int it = 0; it < ITERS; ++it) {
        const int cur = it & 1;
        if (it + 1 < ITERS) {
            const int nb = (it + 1) & 1, kb = (it + 1) * KC;
            if constexpr (ACVT) loadA_cvt(kb);
            else issueA_async(nb, kb);
            issueB(nb, kb);
            cpcommit();
            cpwait<1>();
        } else {
            cpwait<0>();
        }
        __syncthreads();

        #pragma unroll
        for (int ks = 0; ks < KC/16; ks++) {
            uint32_t a[4][4], b[2][4];
            #pragma unroll
            for (int i = 0; i < 4; i++) {
                int row = wr*64 + i*16 + (lane & 15);
                int col = ks*16 + ((lane >> 4) << 3);
                LDSM4(a[i], sbase + (uint32_t)(cur*STAGE + row*LDA_S + col)*2);
            }
            #pragma unroll
            for (int t = 0; t < 2; t++) {
                if constexpr (BTR) {
                    int row = ks*16 + (lane & 7) + (((lane >> 3) & 1) << 3);
                    int col = wc*32 + t*16 + ((lane >> 4) << 3);
                    LDSM4T(b[t], sbase + (uint32_t)(cur*STAGE + ABUF + row*LDB_T + col)*2);
                } else {
                    int row = wc*32 + t*16 + (lane & 7) + ((lane >> 4) << 3);
                    int col = ks*16 + (((lane >> 3) & 1) << 3);
                    LDSM4(b[t], sbase + (uint32_t)(cur*STAGE + ABUF + row*LDA_S + col)*2);
                }
            }
            #pragma unroll
            for (int i = 0; i < 4; i++)
                #pragma unroll
                for (int t = 0; t < 2; t++) {
                    mma16816(acc[i][2*t],   a[i], b[t][0], b[t][1]);
                    mma16816(acc[i][2*t+1], a[i], b[t][2], b[t][3]);
                }
        }
        if (it + 1 < ITERS) {
            if constexpr (ACVT) stsA_cvt((it + 1) & 1);
        }
        __syncthreads();
    }

    // ---- epilogue: direct from mma accumulators ----
    const int g = lane >> 2, tig = lane & 3;
    float bb0[4], bb1[4];
    if constexpr (MODE == 0 || MODE == 4) {
        #pragma unroll
        for (int j = 0; j < 4; j++) {
            int gc = colBase + wc*32 + j*8 + tig*2;
            bb0[j] = __ldg(&bias_p[gc]);
            bb1[j] = __ldg(&bias_p[gc + 1]);
        }
    }
    const float scale = 0.04419417382415922f;   // 1/sqrt(512)
    __half* CoutH = (__half*)Cg + (MODE == 0 ? (size_t)z * QKV_SPAN : 0);

    #pragma unroll
    for (int i = 0; i < 4; i++) {
        int r0 = rowBase + wr*64 + i*16 + g;
        #pragma unroll
        for (int rr = 0; rr < 2; rr++) {
            int gr = r0 + rr*8;
            #pragma unroll
            for (int j = 0; j < 4; j++) {
                float c0 = acc[i][j][rr*2 + 0], c1 = acc[i][j][rr*2 + 1];
                int gc = colBase + wc*32 + j*8 + tig*2;
                if constexpr (MODE == 0) {
                    int b = gr >> 14, n = (gr >> 3) & 2047, ch = gr & 7;
                    int zz = (b << 3) | ch;
                    *(__half2*)(CoutH + ((size_t)zz*NSEQ + n)*DM + gc) =
                        __floats2half2_rn(c0 + bb0[j], c1 + bb1[j]);
                } else if constexpr (MODE == 2) {
                    *(__half2*)((__half*)Cg + ((size_t)z*NSEQ + gr)*NSEQ + gc) =
                        __floats2half2_rn(c0 * scale, c1 * scale);
                } else if constexpr (MODE == 3) {
                    *(__half2*)((__half*)Cg + ((size_t)z*NSEQ + gr)*DM + gc) =
                        __floats2half2_rn(c0, c1);
                } else {  // MODE 4: final output, never re-read -> streaming store
                    int b = gr >> 14, ch = (gr >> 11) & 7, n = gr & 2047;
                    int rm = (b << 14) | (n << 3) | ch;
                    float2 o;
                    o.x = fmaxf(c0 + bb0[j], 0.f);
                    o.y = fmaxf(c1 + bb1[j], 0.f);
                    __stcs((float2*)((float*)Cg + (size_t)rm*DM + gc), o);
                }
            }
        }
    }
}

// ---------------------------------------------------------------------------
// W transpose + fp16 convert, all 4 matrices in one launch (z selects).
// ---------------------------------------------------------------------------
__global__ __launch_bounds__(256) void prep_w_kernel(W4 ws, __half* __restrict__ Wt)
{
    __shared__ float t[32][33];
    const float* W = ws.w[blockIdx.z];
    __half* out = Wt + (size_t)blockIdx.z * DM * DM;
    const int bx = blockIdx.x * 32;   // out
    const int by = blockIdx.y * 32;   // in
    const int tx = threadIdx.x & 31;
    const int ty = threadIdx.x >> 5;  // 0..7
    #pragma unroll
    for (int i = 0; i < 4; i++) {
        int r = ty * 4 + i;
        t[r][tx] = W[(size_t)(by + r) * DM + bx + tx];
    }
    __syncthreads();
    #pragma unroll
    for (int i = 0; i < 4; i++) {
        int r = ty * 4 + i;   // out-local
        out[(size_t)(bx + r) * DM + by + tx] = __float2half_rn(t[tx][r]);
    }
}

// ---------------------------------------------------------------------------
// Softmax: warp per row. fp16 scores in; fp32 attn out (streaming) + fp16
// normalized back in place for the AV GEMM.
// ---------------------------------------------------------------------------
__global__ __launch_bounds__(256) void softmax_kernel(
    __half* __restrict__ Sh, float* __restrict__ Af)
{
    const int row  = blockIdx.x * 8 + (threadIdx.x >> 5);
    const int lane = threadIdx.x & 31;
    __half* p = Sh + (size_t)row * NSEQ;
    float*  o = Af + (size_t)row * NSEQ;

    uint2 hv[16];
    #pragma unroll
    for (int j = 0; j < 16; j++)
        hv[j] = *(const uint2*)(p + lane*4 + j*128);

    float v[64];
    #pragma unroll
    for (int j = 0; j < 16; j++) {
        float2 a = __half22float2(*(__half2*)&hv[j].x);
        float2 b = __half22float2(*(__half2*)&hv[j].y);
        v[4*j+0] = a.x; v[4*j+1] = a.y; v[4*j+2] = b.x; v[4*j+3] = b.y;
    }

    float mx = v[0];
    #pragma unroll
    for (int i = 1; i < 64; i++) mx = fmaxf(mx, v[i]);
    #pragma unroll
    for (int s = 16; s > 0; s >>= 1)
        mx = fmaxf(mx, __shfl_xor_sync(0xffffffffu, mx, s));

    float sum = 0.f;
    #pragma unroll
    for (int i = 0; i < 64; i++) { v[i] = __expf(v[i] - mx); sum += v[i]; }
    #pragma unroll
    for (int s = 16; s > 0; s >>= 1)
        sum += __shfl_xor_sync(0xffffffffu, sum, s);
    const float inv = 1.f / sum;

    #pragma unroll
    for (int j = 0; j < 16; j++) {
        float4 f;
        f.x = v[4*j+0] * inv; f.y = v[4*j+1] * inv;
        f.z = v[4*j+2] * inv; f.w = v[4*j+3] * inv;
        __stcs((float4*)(o + lane*4 + j*128), f);   // fp32 attn: never re-read
        __half2 h0 = __floats2half2_rn(f.x, f.y);
        __half2 h1 = __floats2half2_rn(f.z, f.w);
        uint2 u; u.x = *(uint32_t*)&h0; u.y = *(uint32_t*)&h1;
        *(uint2*)(p + lane*4 + j*128) = u;
    }
}

// ---------------------------------------------------------------------------
#define SMEM_BYTES (2 * STAGE * 2)   // 110592

extern "C" void kernel_launch(void* const* d_in, const int* in_sizes, int n_in,
                              void* d_out, int out_size)
{
    const float* q  = (const float*)d_in[0];
    const float* k  = (const float*)d_in[1];
    const float* v  = (const float*)d_in[2];
    const float* Wq = (const float*)d_in[3];
    const float* bq = (const float*)d_in[4];
    const float* Wk = (const float*)d_in[5];
    const float* bk = (const float*)d_in[6];
    const float* Wv = (const float*)d_in[7];
    const float* bv = (const float*)d_in[8];
    const float* Wo = (const float*)d_in[9];
    const float* bo = (const float*)d_in[10];

    float* out  = (float*)d_out;               // [b,n,c,d]
    float* attn = out + OUT_OFF_ATTN;          // [b,c,n,m]

    void *pqkv, *pc, *ps, *pw;
    cudaGetSymbolAddress(&pqkv, g_qkv);
    cudaGetSymbolAddress(&pc, g_ctx);
    cudaGetSymbolAddress(&ps, g_sc);
    cudaGetSymbolAddress(&pw, g_wt);
    __half* qkv = (__half*)pqkv;
    __half* ctx = (__half*)pc;
    __half* sc  = (__half*)ps;
    __half* wt  = (__half*)pw;

    cudaFuncSetAttribute(gemm_mma<0>, cudaFuncAttributeMaxDynamicSharedMemorySize, SMEM_BYTES);
    cudaFuncSetAttribute(gemm_mma<2>, cudaFuncAttributeMaxDynamicSharedMemorySize, SMEM_BYTES);
    cudaFuncSetAttribute(gemm_mma<3>, cudaFuncAttributeMaxDynamicSharedMemorySize, SMEM_BYTES);
    cudaFuncSetAttribute(gemm_mma<4>, cudaFuncAttributeMaxDynamicSharedMemorySize, SMEM_BYTES);

    P3 none = {};

    // transpose + convert all four weights in one launch
    W4 ws; ws.w[0] = Wq; ws.w[1] = Wk; ws.w[2] = Wv; ws.w[3] = Wo;
    prep_w_kernel<<<dim3(16, 16, 4), 256>>>(ws, wt);

    // q/k/v projections fused into one launch (z picks input/W/bias/out)
    P3 pp;
    pp.a[0] = q;  pp.a[1] = k;  pp.a[2] = v;
    pp.b[0] = bq; pp.b[1] = bk; pp.b[2] = bv;
    gemm_mma<0><<<dim3(2, 512, 3), NTHR, SMEM_BYTES>>>(nullptr, wt, nullptr, qkv, pp);

    __half* qp = qkv;
    __half* kp = qkv + QKV_SPAN;
    __half* vp = qkv + 2*QKV_SPAN;

    // scores: per z, M=N=2048, K=512, fp16 out to g_sc
    gemm_mma<2><<<dim3(8, 16, BCN), NTHR, SMEM_BYTES>>>(qp, kp, nullptr, sc, none);

    // softmax: fp16 in -> fp32 attn (streaming) + fp16 normalized in place
    softmax_kernel<<<BCN * NSEQ / 8, 256>>>(sc, attn);

    // AV: per z, M=2048, N=512, K=2048
    gemm_mma<3><<<dim3(2, 16, BCN), NTHR, SMEM_BYTES>>>(sc, vp, nullptr, ctx, none);

    // out projection
    gemm_mma<4><<<dim3(2, 512, 1), NTHR, SMEM_BYTES>>>(ctx, wt + 3*(size_t)DM*DM, bo, out, none);
}

// round 9
// speedup vs baseline: 1.0341x; 1.0341x over previous
#include <cuda_runtime.h>
#include <cuda_fp16.h>
#include <cstdint>
#include <math.h>

// ---------------------------------------------------------------------------
#define DM     512
#define NSEQ   2048
#define CH     8
#define BATCH  4
#define BCN    (BATCH*CH)            // 32 attention batches
#define MROWS  (BATCH*NSEQ*CH)       // 65536 projection rows
#define OUT_OFF_ATTN ((size_t)BATCH*NSEQ*CH*DM)
#define QKV_SPAN ((size_t)BCN*NSEQ*DM)

// Scratch (device globals — allocation-free per harness rules)
__device__ __half g_qkv[3*QKV_SPAN];              // qp | kp | vp, each [z][n][d]
__device__ __half g_ctx[QKV_SPAN];                // [z][n][d]
__device__ __half g_sc [(size_t)BCN*NSEQ*NSEQ];   // fp16 scores / normalized attn
__device__ __half g_wt [4*(size_t)DM*DM];         // W^T as [out][in], fp16

struct P3 { const float* a[3]; const float* b[3]; };
struct W4 { const float* w[4]; };

// ---------------------------------------------------------------------------
__device__ __forceinline__ uint32_t smem_u32(const void* p) {
    uint32_t a;
    asm("{ .reg .u64 t; cvta.to.shared.u64 t, %1; cvt.u32.u64 %0, t; }"
        : "=r"(a) : "l"(p));
    return a;
}
__device__ __forceinline__ void cpa16(uint32_t d, const void* s) {
    asm volatile("cp.async.cg.shared.global [%0], [%1], 16;" :: "r"(d), "l"(s));
}
__device__ __forceinline__ void cpcommit() {
    asm volatile("cp.async.commit_group;" ::: "memory");
}
template<int N> __device__ __forceinline__ void cpwait() {
    asm volatile("cp.async.wait_group %0;" :: "n"(N) : "memory");
}
#define LDSM4(r, a)                                                           \
    asm volatile("ldmatrix.sync.aligned.m8n8.x4.shared.b16 {%0,%1,%2,%3}, [%4];" \
        : "=r"((r)[0]), "=r"((r)[1]), "=r"((r)[2]), "=r"((r)[3]) : "r"(a))
#define LDSM4T(r, a)                                                          \
    asm volatile("ldmatrix.sync.aligned.m8n8.x4.trans.shared.b16 {%0,%1,%2,%3}, [%4];" \
        : "=r"((r)[0]), "=r"((r)[1]), "=r"((r)[2]), "=r"((r)[3]) : "r"(a))

__device__ __forceinline__ void mma16816(float* c, const uint32_t* a,
                                         uint32_t b0, uint32_t b1) {
    asm volatile(
        "mma.sync.aligned.m16n8k16.row.col.f32.f16.f16.f32 "
        "{%0,%1,%2,%3}, {%4,%5,%6,%7}, {%8,%9}, {%0,%1,%2,%3};"
        : "+f"(c[0]), "+f"(c[1]), "+f"(c[2]), "+f"(c[3])
        : "r"(a[0]), "r"(a[1]), "r"(a[2]), "r"(a[3]), "r"(b0), "r"(b1));
}

// ---------------------------------------------------------------------------
// Block tile 128x256xKC(=64), 256 threads = 8 warps of 64x64, 3-stage pipe.
// MODE 0: projections q/k/v (z picks input/W/bias/out), f32 A, half out
// MODE 2: scores      C = scale * Q @ K^T, half in, HALF out (to g_sc)
// MODE 3: AV          C = attnH @ V, A half, V loaded [m][d] w/ ldmatrix.trans
// MODE 4: out proj    C = relu(ctx(h)@Wo^T + b), remap (b,c,n)->(b,n,c), f32
// ---------------------------------------------------------------------------
#define KC     64
#define LDA_S  72          // halves: 64 + 8 pad
#define LDB_T  264         // halves for BTR tiles (256 + 8 pad)
#define ABUF   (128*LDA_S)             // 9216 halves
#define BBUF   (256*LDA_S)             // 18432 halves (>= 64*LDB_T = 16896)
#define STAGE  (ABUF + BBUF)
#define NSTG   3
#define NTHR   256

template<int MODE>
__global__ __launch_bounds__(NTHR) void gemm_mma(
    const void* __restrict__ Ag, const __half* __restrict__ Bg,
    const float* __restrict__ bias, void* __restrict__ Cg, P3 pp)
{
    extern __shared__ __half sh[];
    constexpr int  K     = (MODE == 3) ? NSEQ : DM;
    constexpr int  ITERS = K / KC;
    constexpr bool ACVT  = (MODE == 0);
    constexpr bool BTR   = (MODE == 3);
    constexpr int  LDAE  = (MODE == 3) ? NSEQ : DM;

    const int tid = threadIdx.x, lane = tid & 31, wid = tid >> 5;
    const int wr = wid >> 2, wc = wid & 3;     // 2 x 4 warps -> 64x64 tiles
    const int z = blockIdx.z;
    const int rowBase = blockIdx.y * 128, colBase = blockIdx.x * 256;

    const float* Af = ACVT ? pp.a[z] : nullptr;
    const float* bias_p = ACVT ? pp.b[z] : bias;
    const __half* Ah = (const __half*)Ag +
        (MODE == 2 ? (size_t)z*NSEQ*DM : MODE == 3 ? (size_t)z*NSEQ*NSEQ : 0);
    const __half* Bp = Bg +
        (MODE == 0 ? (size_t)z*DM*DM :
         (MODE == 2 || MODE == 3) ? (size_t)z*NSEQ*DM : 0);

    const uint32_t sbase = smem_u32(sh);

    float acc[4][8][4];
    #pragma unroll
    for (int i = 0; i < 4; i++)
        #pragma unroll
        for (int j = 0; j < 8; j++)
            #pragma unroll
            for (int q = 0; q < 4; q++) acc[i][j][q] = 0.f;

    // ---- loaders (256 threads) ----
    const int avr = tid & 127;      // CVT: row
    const int avh = tid >> 7;       // CVT: 32-col half (0/1)
    float4 fA[8];

    auto loadA_cvt = [&](int kb) {
        const float* s = Af + (size_t)(rowBase + avr) * LDAE + kb + avh * 32;
        #pragma unroll
        for (int u = 0; u < 8; u++) fA[u] = *(const float4*)(s + u*4);
    };
    auto stsA_cvt = [&](int buf) {
        __half hv[32];
        #pragma unroll
        for (int u = 0; u < 8; u++) {
            hv[u*4+0] = __float2half_rn(fA[u].x);
            hv[u*4+1] = __float2half_rn(fA[u].y);
            hv[u*4+2] = __float2half_rn(fA[u].z);
            hv[u*4+3] = __float2half_rn(fA[u].w);
        }
        __half* d = sh + buf*STAGE + avr*LDA_S + avh*32;
        #pragma unroll
        for (int u = 0; u < 4; u++)
            *((uint4*)d + u) = ((uint4*)hv)[u];
    };
    auto issueA_async = [&](int buf, int kb) {
        #pragma unroll
        for (int i = 0; i < 4; i++) {
            int idx = tid + i*NTHR;
            int h = idx & 7, r = idx >> 3;
            cpa16(sbase + (uint32_t)(buf*STAGE + r*LDA_S + h*8)*2,
                  Ah + (size_t)(rowBase + r)*LDAE + kb + h*8);
        }
    };
    auto issueB = [&](int buf, int kb) {
        if constexpr (BTR) {
            #pragma unroll
            for (int i = 0; i < 8; i++) {
                int idx = tid + i*NTHR;
                int r = idx >> 5, h = idx & 31;
                cpa16(sbase + (uint32_t)(buf*STAGE + ABUF + r*LDB_T + h*8)*2,
                      Bp + (size_t)(kb + r)*DM + colBase + h*8);
            }
        } else {
            #pragma unroll
            for (int i = 0; i < 8; i++) {
                int idx = tid + i*NTHR;
                int h = idx & 7, r = idx >> 3;
                cpa16(sbase + (uint32_t)(buf*STAGE + ABUF + r*LDA_S + h*8)*2,
                      Bp + (size_t)(colBase + r)*DM + kb + h*8);
            }
        }
    };

    // ---- prologue: stage 0 and 1 ----
    if constexpr (ACVT) {
        loadA_cvt(0);  stsA_cvt(0);
        loadA_cvt(KC); stsA_cvt(1);
        issueB(0, 0);  cpcommit();
        issueB(1, KC); cpcommit();
    } else {
        issueA_async(0, 0);  issueB(0, 0);  cpcommit();
        issueA_async(1, KC); issueB(1, KC); cpcommit();
    }

    // ---- main loop: single __syncthreads per iteration ----
    for (int it = 0; it < ITERS; ++it) {
        const int cur = it % NSTG;
        if (it + 1 < ITERS) cpwait<1>(); else cpwait<0>();
        __syncthreads();

        const bool pf = (it + 2 < ITERS);
        const int  nb = (it + 2) % NSTG, kb = (it + 2) * KC;
        if (pf) {
            if constexpr (ACVT) { loadA_cvt(kb); issueB(nb, kb); cpcommit(); }
            else { issueA_async(nb, kb); issueB(nb, kb); cpcommit(); }
        }

        #pragma unroll
        for (int ks = 0; ks < KC/16; ks++) {
            uint32_t a[4][4], b[4][4];
            #pragma unroll
            for (int i = 0; i < 4; i++) {
                int row = wr*64 + i*16 + (lane & 15);
                int col = ks*16 + ((lane >> 4) << 3);
                LDSM4(a[i], sbase + (uint32_t)(cur*STAGE + row*LDA_S + col)*2);
            }
            #pragma unroll
            for (int t = 0; t < 4; t++) {
                if constexpr (BTR) {
                    int row = ks*16 + (lane & 7) + (((lane >> 3) & 1) << 3);
                    int col = wc*64 + t*16 + ((lane >> 4) << 3);
                    LDSM4T(b[t], sbase + (uint32_t)(cur*STAGE + ABUF + row*LDB_T + col)*2);
                } else {
                    int row = wc*64 + t*16 + (lane & 7) + ((lane >> 4) << 3);
                    int col = ks*16 + (((lane >> 3) & 1) << 3);
                    LDSM4(b[t], sbase + (uint32_t)(cur*STAGE + ABUF + row*LDA_S + col)*2);
                }
            }
            #pragma unroll
            for (int i = 0; i < 4; i++)
                #pragma unroll
                for (int t = 0; t < 4; t++) {
                    mma16816(acc[i][2*t],   a[i], b[t][0], b[t][1]);
                    mma16816(acc[i][2*t+1], a[i], b[t][2], b[t][3]);
                }
        }
        if (pf) {
            if constexpr (ACVT) stsA_cvt(nb);   // into stage it+2 (safe: sync passed)
        }
    }

    // ---- epilogue: direct from mma accumulators ----
    const int g = lane >> 2, tig = lane & 3;
    float bb0[8], bb1[8];
    if constexpr (MODE == 0 || MODE == 4) {
        #pragma unroll
        for (int j = 0; j < 8; j++) {
            int gc = colBase + wc*64 + j*8 + tig*2;
            bb0[j] = __ldg(&bias_p[gc]);
            bb1[j] = __ldg(&bias_p[gc + 1]);
        }
    }
    const float scale = 0.04419417382415922f;   // 1/sqrt(512)
    __half* CoutH = (__half*)Cg + (MODE == 0 ? (size_t)z * QKV_SPAN : 0);

    #pragma unroll
    for (int i = 0; i < 4; i++) {
        int r0 = rowBase + wr*64 + i*16 + g;
        #pragma unroll
        for (int rr = 0; rr < 2; rr++) {
            int gr = r0 + rr*8;
            #pragma unroll
            for (int j = 0; j < 8; j++) {
                float c0 = acc[i][j][rr*2 + 0], c1 = acc[i][j][rr*2 + 1];
                int gc = colBase + wc*64 + j*8 + tig*2;
                if constexpr (MODE == 0) {
                    int b = gr >> 14, n = (gr >> 3) & 2047, ch = gr & 7;
                    int zz = (b << 3) | ch;
                    *(__half2*)(CoutH + ((size_t)zz*NSEQ + n)*DM + gc) =
                        __floats2half2_rn(c0 + bb0[j], c1 + bb1[j]);
                } else if constexpr (MODE == 2) {
                    // scores: re-read only after full softmax pass (256MB) —
                    // streaming store, keep L2 for qp/kp tiles
                    __half2 h = __floats2half2_rn(c0 * scale, c1 * scale);
                    __stcs((__half2*)((__half*)Cg + ((size_t)z*NSEQ + gr)*NSEQ + gc), h);
                } else if constexpr (MODE == 3) {
                    *(__half2*)((__half*)Cg + ((size_t)z*NSEQ + gr)*DM + gc) =
                        __floats2half2_rn(c0, c1);
                } else {  // MODE 4: final output, never re-read -> streaming store
                    int b = gr >> 14, ch = (gr >> 11) & 7, n = gr & 2047;
                    int rm = (b << 14) | (n << 3) | ch;
                    float2 o;
                    o.x = fmaxf(c0 + bb0[j], 0.f);
                    o.y = fmaxf(c1 + bb1[j], 0.f);
                    __stcs((float2*)((float*)Cg + (size_t)rm*DM + gc), o);
                }
            }
        }
    }
}

// ---------------------------------------------------------------------------
// W transpose + fp16 convert, all 4 matrices in one launch (z selects).
// ---------------------------------------------------------------------------
__global__ __launch_bounds__(256) void prep_w_kernel(W4 ws, __half* __restrict__ Wt)
{
    __shared__ float t[32][33];
    const float* W = ws.w[blockIdx.z];
    __half* out = Wt + (size_t)blockIdx.z * DM * DM;
    const int bx = blockIdx.x * 32;   // out
    const int by = blockIdx.y * 32;   // in
    const int tx = threadIdx.x & 31;
    const int ty = threadIdx.x >> 5;  // 0..7
    #pragma unroll
    for (int i = 0; i < 4; i++) {
        int r = ty * 4 + i;
        t[r][tx] = W[(size_t)(by + r) * DM + bx + tx];
    }
    __syncthreads();
    #pragma unroll
    for (int i = 0; i < 4; i++) {
        int r = ty * 4 + i;   // out-local
        out[(size_t)(bx + r) * DM + by + tx] = __float2half_rn(t[tx][r]);
    }
}

// ---------------------------------------------------------------------------
// Softmax: warp per row. fp16 scores in; fp32 attn out (streaming) + fp16
// normalized back in place for the AV GEMM.
// ---------------------------------------------------------------------------
__global__ __launch_bounds__(256) void softmax_kernel(
    __half* __restrict__ Sh, float* __restrict__ Af)
{
    const int row  = blockIdx.x * 8 + (threadIdx.x >> 5);
    const int lane = threadIdx.x & 31;
    __half* p = Sh + (size_t)row * NSEQ;
    float*  o = Af + (size_t)row * NSEQ;

    uint2 hv[16];
    #pragma unroll
    for (int j = 0; j < 16; j++)
        hv[j] = *(const uint2*)(p + lane*4 + j*128);

    float v[64];
    #pragma unroll
    for (int j = 0; j < 16; j++) {
        float2 a = __half22float2(*(__half2*)&hv[j].x);
        float2 b = __half22float2(*(__half2*)&hv[j].y);
        v[4*j+0] = a.x; v[4*j+1] = a.y; v[4*j+2] = b.x; v[4*j+3] = b.y;
    }

    float mx = v[0];
    #pragma unroll
    for (int i = 1; i < 64; i++) mx = fmaxf(mx, v[i]);
    #pragma unroll
    for (int s = 16; s > 0; s >>= 1)
        mx = fmaxf(mx, __shfl_xor_sync(0xffffffffu, mx, s));

    float sum = 0.f;
    #pragma unroll
    for (int i = 0; i < 64; i++) { v[i] = __expf(v[i] - mx); sum += v[i]; }
    #pragma unroll
    for (int s = 16; s > 0; s >>= 1)
        sum += __shfl_xor_sync(0xffffffffu, sum, s);
    const float inv = 1.f / sum;

    #pragma unroll
    for (int j = 0; j < 16; j++) {
        float4 f;
        f.x = v[4*j+0] * inv; f.y = v[4*j+1] * inv;
        f.z = v[4*j+2] * inv; f.w = v[4*j+3] * inv;
        __stcs((float4*)(o + lane*4 + j*128), f);   // fp32 attn: never re-read
        __half2 h0 = __floats2half2_rn(f.x, f.y);
        __half2 h1 = __floats2half2_rn(f.z, f.w);
        uint2 u; u.x = *(uint32_t*)&h0; u.y = *(uint32_t*)&h1;
        *(uint2*)(p + lane*4 + j*128) = u;
    }
}

// ---------------------------------------------------------------------------
#define SMEM_BYTES (NSTG * STAGE * 2)   // 165888

extern "C" void kernel_launch(void* const* d_in, const int* in_sizes, int n_in,
                              void* d_out, int out_size)
{
    const float* q  = (const float*)d_in[0];
    const float* k  = (const float*)d_in[1];
    const float* v  = (const float*)d_in[2];
    const float* Wq = (const float*)d_in[3];
    const float* bq = (const float*)d_in[4];
    const float* Wk = (const float*)d_in[5];
    const float* bk = (const float*)d_in[6];
    const float* Wv = (const float*)d_in[7];
    const float* bv = (const float*)d_in[8];
    const float* Wo = (const float*)d_in[9];
    const float* bo = (const float*)d_in[10];

    float* out  = (float*)d_out;               // [b,n,c,d]
    float* attn = out + OUT_OFF_ATTN;          // [b,c,n,m]

    void *pqkv, *pc, *ps, *pw;
    cudaGetSymbolAddress(&pqkv, g_qkv);
    cudaGetSymbolAddress(&pc, g_ctx);
    cudaGetSymbolAddress(&ps, g_sc);
    cudaGetSymbolAddress(&pw, g_wt);
    __half* qkv = (__half*)pqkv;
    __half* ctx = (__half*)pc;
    __half* sc  = (__half*)ps;
    __half* wt  = (__half*)pw;

    cudaFuncSetAttribute(gemm_mma<0>, cudaFuncAttributeMaxDynamicSharedMemorySize, SMEM_BYTES);
    cudaFuncSetAttribute(gemm_mma<2>, cudaFuncAttributeMaxDynamicSharedMemorySize, SMEM_BYTES);
    cudaFuncSetAttribute(gemm_mma<3>, cudaFuncAttributeMaxDynamicSharedMemorySize, SMEM_BYTES);
    cudaFuncSetAttribute(gemm_mma<4>, cudaFuncAttributeMaxDynamicSharedMemorySize, SMEM_BYTES);

    P3 none = {};

    // transpose + convert all four weights in one launch
    W4 ws; ws.w[0] = Wq; ws.w[1] = Wk; ws.w[2] = Wv; ws.w[3] = Wo;
    prep_w_kernel<<<dim3(16, 16, 4), 256>>>(ws, wt);

    // q/k/v projections fused into one launch (z picks input/W/bias/out)
    P3 pp;
    pp.a[0] = q;  pp.a[1] = k;  pp.a[2] = v;
    pp.b[0] = bq; pp.b[1] = bk; pp.b[2] = bv;
    gemm_mma<0><<<dim3(2, 512, 3), NTHR, SMEM_BYTES>>>(nullptr, wt, nullptr, qkv, pp);

    __half* qp = qkv;
    __half* kp = qkv + QKV_SPAN;
    __half* vp = qkv + 2*QKV_SPAN;

    // scores: per z, M=N=2048, K=512, fp16 out to g_sc
    gemm_mma<2><<<dim3(8, 16, BCN), NTHR, SMEM_BYTES>>>(qp, kp, nullptr, sc, none);

    // softmax: fp16 in -> fp32 attn (streaming) + fp16 normalized in place
    softmax_kernel<<<BCN * NSEQ / 8, 256>>>(sc, attn);

    // AV: per z, M=2048, N=512, K=2048
    gemm_mma<3><<<dim3(2, 16, BCN), NTHR, SMEM_BYTES>>>(sc, vp, nullptr, ctx, none);

    // out projection
    gemm_mma<4><<<dim3(2, 512, 1), NTHR, SMEM_BYTES>>>(ctx, wt + 3*(size_t)DM*DM, bo, out, none);
}

// round 10
// speedup vs baseline: 1.0466x; 1.0120x over previous
#include <cuda_runtime.h>
#include <cuda_fp16.h>
#include <cstdint>
#include <math.h>

// ---------------------------------------------------------------------------
#define DM     512
#define NSEQ   2048
#define CH     8
#define BATCH  4
#define BCN    (BATCH*CH)            // 32 attention batches
#define MROWS  (BATCH*NSEQ*CH)       // 65536 projection rows
#define OUT_OFF_ATTN ((size_t)BATCH*NSEQ*CH*DM)
#define QKV_SPAN ((size_t)BCN*NSEQ*DM)

// Scratch (device globals — allocation-free per harness rules)
__device__ __half g_qkv[3*QKV_SPAN];              // qp | kp | vp, each [z][n][d]
__device__ __half g_ctx[QKV_SPAN];                // [z][n][d]
__device__ __half g_sc [(size_t)BCN*NSEQ*NSEQ];   // fp16 scores / normalized attn
__device__ __half g_wt [4*(size_t)DM*DM];         // W^T as [out][in], fp16

struct P3 { const float* a[3]; const float* b[3]; };
struct W4 { const float* w[4]; };

// ---------------------------------------------------------------------------
__device__ __forceinline__ uint32_t smem_u32(const void* p) {
    uint32_t a;
    asm("{ .reg .u64 t; cvta.to.shared.u64 t, %1; cvt.u32.u64 %0, t; }"
        : "=r"(a) : "l"(p));
    return a;
}
__device__ __forceinline__ void cpa16(uint32_t d, const void* s) {
    asm volatile("cp.async.cg.shared.global [%0], [%1], 16;" :: "r"(d), "l"(s));
}
__device__ __forceinline__ void cpcommit() {
    asm volatile("cp.async.commit_group;" ::: "memory");
}
template<int N> __device__ __forceinline__ void cpwait() {
    asm volatile("cp.async.wait_group %0;" :: "n"(N) : "memory");
}
#define LDSM4(r, a)                                                           \
    asm volatile("ldmatrix.sync.aligned.m8n8.x4.shared.b16 {%0,%1,%2,%3}, [%4];" \
        : "=r"((r)[0]), "=r"((r)[1]), "=r"((r)[2]), "=r"((r)[3]) : "r"(a))
#define LDSM4T(r, a)                                                          \
    asm volatile("ldmatrix.sync.aligned.m8n8.x4.trans.shared.b16 {%0,%1,%2,%3}, [%4];" \
        : "=r"((r)[0]), "=r"((r)[1]), "=r"((r)[2]), "=r"((r)[3]) : "r"(a))

__device__ __forceinline__ void mma16816(float* c, const uint32_t* a,
                                         uint32_t b0, uint32_t b1) {
    asm volatile(
        "mma.sync.aligned.m16n8k16.row.col.f32.f16.f16.f32 "
        "{%0,%1,%2,%3}, {%4,%5,%6,%7}, {%8,%9}, {%0,%1,%2,%3};"
        : "+f"(c[0]), "+f"(c[1]), "+f"(c[2]), "+f"(c[3])
        : "r"(a[0]), "r"(a[1]), "r"(a[2]), "r"(a[3]), "r"(b0), "r"(b1));
}

// ---------------------------------------------------------------------------
// Block tile 128x256xKC(=64), 256 threads = 8 warps of 64x64, 3-stage pipe,
// software-pipelined fragment loads (double-buffered LDSM).
// MODE 0: projections q/k/v (z picks input/W/bias/out), f32 A, half out
// MODE 2: scores      C = scale * Q @ K^T, half in, HALF out (to g_sc)
// MODE 3: AV          C = attnH @ V, A half, V loaded [m][d] w/ ldmatrix.trans
// MODE 4: out proj    C = relu(ctx(h)@Wo^T + b), remap (b,c,n)->(b,n,c), f32
// ---------------------------------------------------------------------------
#define KC     64
#define LDA_S  72          // halves: 64 + 8 pad
#define LDB_T  264         // halves for BTR tiles (256 + 8 pad)
#define ABUF   (128*LDA_S)             // 9216 halves
#define BBUF   (256*LDA_S)             // 18432 halves (>= 64*LDB_T = 16896)
#define STAGE  (ABUF + BBUF)
#define NSTG   3
#define NTHR   256

template<int MODE>
__global__ __launch_bounds__(NTHR) void gemm_mma(
    const void* __restrict__ Ag, const __half* __restrict__ Bg,
    const float* __restrict__ bias, void* __restrict__ Cg, P3 pp)
{
    extern __shared__ __half sh[];
    constexpr int  K     = (MODE == 3) ? NSEQ : DM;
    constexpr int  ITERS = K / KC;
    constexpr bool ACVT  = (MODE == 0);
    constexpr bool BTR   = (MODE == 3);
    constexpr int  LDAE  = (MODE == 3) ? NSEQ : DM;

    const int tid = threadIdx.x, lane = tid & 31, wid = tid >> 5;
    const int wr = wid >> 2, wc = wid & 3;     // 2 x 4 warps -> 64x64 tiles
    const int z = blockIdx.z;
    const int rowBase = blockIdx.y * 128, colBase = blockIdx.x * 256;

    const float* Af = ACVT ? pp.a[z] : nullptr;
    const float* bias_p = ACVT ? pp.b[z] : bias;
    const __half* Ah = (const __half*)Ag +
        (MODE == 2 ? (size_t)z*NSEQ*DM : MODE == 3 ? (size_t)z*NSEQ*NSEQ : 0);
    const __half* Bp = Bg +
        (MODE == 0 ? (size_t)z*DM*DM :
         (MODE == 2 || MODE == 3) ? (size_t)z*NSEQ*DM : 0);

    const uint32_t sbase = smem_u32(sh);

    float acc[4][8][4];
    #pragma unroll
    for (int i = 0; i < 4; i++)
        #pragma unroll
        for (int j = 0; j < 8; j++)
            #pragma unroll
            for (int q = 0; q < 4; q++) acc[i][j][q] = 0.f;

    // ---- loaders (256 threads) ----
    const int avr = tid & 127;      // CVT: row
    const int avh = tid >> 7;       // CVT: 32-col half (0/1)
    float4 fA[8];

    auto loadA_cvt = [&](int kb) {
        const float* s = Af + (size_t)(rowBase + avr) * LDAE + kb + avh * 32;
        #pragma unroll
        for (int u = 0; u < 8; u++) fA[u] = *(const float4*)(s + u*4);
    };
    auto stsA_cvt = [&](int buf) {
        __half hv[32];
        #pragma unroll
        for (int u = 0; u < 8; u++) {
            hv[u*4+0] = __float2half_rn(fA[u].x);
            hv[u*4+1] = __float2half_rn(fA[u].y);
            hv[u*4+2] = __float2half_rn(fA[u].z);
            hv[u*4+3] = __float2half_rn(fA[u].w);
        }
        __half* d = sh + buf*STAGE + avr*LDA_S + avh*32;
        #pragma unroll
        for (int u = 0; u < 4; u++)
            *((uint4*)d + u) = ((uint4*)hv)[u];
    };
    auto issueA_async = [&](int buf, int kb) {
        #pragma unroll
        for (int i = 0; i < 4; i++) {
            int idx = tid + i*NTHR;
            int h = idx & 7, r = idx >> 3;
            cpa16(sbase + (uint32_t)(buf*STAGE + r*LDA_S + h*8)*2,
                  Ah + (size_t)(rowBase + r)*LDAE + kb + h*8);
        }
    };
    auto issueB = [&](int buf, int kb) {
        if constexpr (BTR) {
            #pragma unroll
            for (int i = 0; i < 8; i++) {
                int idx = tid + i*NTHR;
                int r = idx >> 5, h = idx & 31;
                cpa16(sbase + (uint32_t)(buf*STAGE + ABUF + r*LDB_T + h*8)*2,
                      Bp + (size_t)(kb + r)*DM + colBase + h*8);
            }
        } else {
            #pragma unroll
            for (int i = 0; i < 8; i++) {
                int idx = tid + i*NTHR;
                int h = idx & 7, r = idx >> 3;
                cpa16(sbase + (uint32_t)(buf*STAGE + ABUF + r*LDA_S + h*8)*2,
                      Bp + (size_t)(colBase + r)*DM + kb + h*8);
            }
        }
    };

    // fragment load for one ks slice (16 K-columns)
    auto load_frags = [&](int cur, int ks, uint32_t (*af)[4], uint32_t (*bf)[4]) {
        #pragma unroll
        for (int i = 0; i < 4; i++) {
            int row = wr*64 + i*16 + (lane & 15);
            int col = ks*16 + ((lane >> 4) << 3);
            LDSM4(af[i], sbase + (uint32_t)(cur*STAGE + row*LDA_S + col)*2);
        }
        #pragma unroll
        for (int t = 0; t < 4; t++) {
            if constexpr (BTR) {
                int row = ks*16 + (lane & 7) + (((lane >> 3) & 1) << 3);
                int col = wc*64 + t*16 + ((lane >> 4) << 3);
                LDSM4T(bf[t], sbase + (uint32_t)(cur*STAGE + ABUF + row*LDB_T + col)*2);
            } else {
                int row = wc*64 + t*16 + (lane & 7) + ((lane >> 4) << 3);
                int col = ks*16 + (((lane >> 3) & 1) << 3);
                LDSM4(bf[t], sbase + (uint32_t)(cur*STAGE + ABUF + row*LDA_S + col)*2);
            }
        }
    };

    // ---- prologue: stage 0 and 1 ----
    if constexpr (ACVT) {
        loadA_cvt(0);  stsA_cvt(0);
        loadA_cvt(KC); stsA_cvt(1);
        issueB(0, 0);  cpcommit();
        issueB(1, KC); cpcommit();
    } else {
        issueA_async(0, 0);  issueB(0, 0);  cpcommit();
        issueA_async(1, KC); issueB(1, KC); cpcommit();
    }

    uint32_t afr[2][4][4], bfr[2][4][4];

    // ---- main loop: single __syncthreads per iteration ----
    for (int it = 0; it < ITERS; ++it) {
        const int cur = it % NSTG;
        if (it + 1 < ITERS) cpwait<1>(); else cpwait<0>();
        __syncthreads();

        const bool pf = (it + 2 < ITERS);
        const int  nb = (it + 2) % NSTG, kb = (it + 2) * KC;
        if (pf) {
            if constexpr (ACVT) { loadA_cvt(kb); issueB(nb, kb); cpcommit(); }
            else { issueA_async(nb, kb); issueB(nb, kb); cpcommit(); }
        }

        // software-pipelined fragments: load ks+1 while computing ks
        load_frags(cur, 0, afr[0], bfr[0]);
        #pragma unroll
        for (int ks = 0; ks < KC/16; ks++) {
            const int pb = ks & 1;
            if (ks + 1 < KC/16)
                load_frags(cur, ks + 1, afr[pb^1], bfr[pb^1]);
            #pragma unroll
            for (int i = 0; i < 4; i++)
                #pragma unroll
                for (int t = 0; t < 4; t++) {
                    mma16816(acc[i][2*t],   afr[pb][i], bfr[pb][t][0], bfr[pb][t][1]);
                    mma16816(acc[i][2*t+1], afr[pb][i], bfr[pb][t][2], bfr[pb][t][3]);
                }
        }
        if (pf) {
            if constexpr (ACVT) stsA_cvt(nb);   // into stage it+2 (safe: sync passed)
        }
    }

    // ---- epilogue: direct from mma accumulators ----
    const int g = lane >> 2, tig = lane & 3;
    float bb0[8], bb1[8];
    if constexpr (MODE == 0 || MODE == 4) {
        #pragma unroll
        for (int j = 0; j < 8; j++) {
            int gc = colBase + wc*64 + j*8 + tig*2;
            bb0[j] = __ldg(&bias_p[gc]);
            bb1[j] = __ldg(&bias_p[gc + 1]);
        }
    }
    const float scale = 0.04419417382415922f;   // 1/sqrt(512)
    __half* CoutH = (__half*)Cg + (MODE == 0 ? (size_t)z * QKV_SPAN : 0);

    #pragma unroll
    for (int i = 0; i < 4; i++) {
        int r0 = rowBase + wr*64 + i*16 + g;
        #pragma unroll
        for (int rr = 0; rr < 2; rr++) {
            int gr = r0 + rr*8;
            #pragma unroll
            for (int j = 0; j < 8; j++) {
                float c0 = acc[i][j][rr*2 + 0], c1 = acc[i][j][rr*2 + 1];
                int gc = colBase + wc*64 + j*8 + tig*2;
                if constexpr (MODE == 0) {
                    int b = gr >> 14, n = (gr >> 3) & 2047, ch = gr & 7;
                    int zz = (b << 3) | ch;
                    *(__half2*)(CoutH + ((size_t)zz*NSEQ + n)*DM + gc) =
                        __floats2half2_rn(c0 + bb0[j], c1 + bb1[j]);
                } else if constexpr (MODE == 2) {
                    __half2 h = __floats2half2_rn(c0 * scale, c1 * scale);
                    __stcs((__half2*)((__half*)Cg + ((size_t)z*NSEQ + gr)*NSEQ + gc), h);
                } else if constexpr (MODE == 3) {
                    *(__half2*)((__half*)Cg + ((size_t)z*NSEQ + gr)*DM + gc) =
                        __floats2half2_rn(c0, c1);
                } else {  // MODE 4: final output, never re-read -> streaming store
                    int b = gr >> 14, ch = (gr >> 11) & 7, n = gr & 2047;
                    int rm = (b << 14) | (n << 3) | ch;
                    float2 o;
                    o.x = fmaxf(c0 + bb0[j], 0.f);
                    o.y = fmaxf(c1 + bb1[j], 0.f);
                    __stcs((float2*)((float*)Cg + (size_t)rm*DM + gc), o);
                }
            }
        }
    }
}

// ---------------------------------------------------------------------------
// W transpose + fp16 convert, all 4 matrices in one launch (z selects).
// ---------------------------------------------------------------------------
__global__ __launch_bounds__(256) void prep_w_kernel(W4 ws, __half* __restrict__ Wt)
{
    __shared__ float t[32][33];
    const float* W = ws.w[blockIdx.z];
    __half* out = Wt + (size_t)blockIdx.z * DM * DM;
    const int bx = blockIdx.x * 32;   // out
    const int by = blockIdx.y * 32;   // in
    const int tx = threadIdx.x & 31;
    const int ty = threadIdx.x >> 5;  // 0..7
    #pragma unroll
    for (int i = 0; i < 4; i++) {
        int r = ty * 4 + i;
        t[r][tx] = W[(size_t)(by + r) * DM + bx + tx];
    }
    __syncthreads();
    #pragma unroll
    for (int i = 0; i < 4; i++) {
        int r = ty * 4 + i;   // out-local
        out[(size_t)(bx + r) * DM + by + tx] = __float2half_rn(t[tx][r]);
    }
}

// ---------------------------------------------------------------------------
// Softmax: warp per row. fp16 scores in; fp32 attn out (streaming) + fp16
// normalized back in place for the AV GEMM.
// ---------------------------------------------------------------------------
__global__ __launch_bounds__(256) void softmax_kernel(
    __half* __restrict__ Sh, float* __restrict__ Af)
{
    const int row  = blockIdx.x * 8 + (threadIdx.x >> 5);
    const int lane = threadIdx.x & 31;
    __half* p = Sh + (size_t)row * NSEQ;
    float*  o = Af + (size_t)row * NSEQ;

    uint2 hv[16];
    #pragma unroll
    for (int j = 0; j < 16; j++)
        hv[j] = *(const uint2*)(p + lane*4 + j*128);

    float v[64];
    #pragma unroll
    for (int j = 0; j < 16; j++) {
        float2 a = __half22float2(*(__half2*)&hv[j].x);
        float2 b = __half22float2(*(__half2*)&hv[j].y);
        v[4*j+0] = a.x; v[4*j+1] = a.y; v[4*j+2] = b.x; v[4*j+3] = b.y;
    }

    float mx = v[0];
    #pragma unroll
    for (int i = 1; i < 64; i++) mx = fmaxf(mx, v[i]);
    #pragma unroll
    for (int s = 16; s > 0; s >>= 1)
        mx = fmaxf(mx, __shfl_xor_sync(0xffffffffu, mx, s));

    float sum = 0.f;
    #pragma unroll
    for (int i = 0; i < 64; i++) { v[i] = __expf(v[i] - mx); sum += v[i]; }
    #pragma unroll
    for (int s = 16; s > 0; s >>= 1)
        sum += __shfl_xor_sync(0xffffffffu, sum, s);
    const float inv = 1.f / sum;

    #pragma unroll
    for (int j = 0; j < 16; j++) {
        float4 f;
        f.x = v[4*j+0] * inv; f.y = v[4*j+1] * inv;
        f.z = v[4*j+2] * inv; f.w = v[4*j+3] * inv;
        __stcs((float4*)(o + lane*4 + j*128), f);   // fp32 attn: never re-read
        __half2 h0 = __floats2half2_rn(f.x, f.y);
        __half2 h1 = __floats2half2_rn(f.z, f.w);
        uint2 u; u.x = *(uint32_t*)&h0; u.y = *(uint32_t*)&h1;
        *(uint2*)(p + lane*4 + j*128) = u;
    }
}

// ---------------------------------------------------------------------------
#define SMEM_BYTES (NSTG * STAGE * 2)   // 165888

extern "C" void kernel_launch(void* const* d_in, const int* in_sizes, int n_in,
                              void* d_out, int out_size)
{
    const float* q  = (const float*)d_in[0];
    const float* k  = (const float*)d_in[1];
    const float* v  = (const float*)d_in[2];
    const float* Wq = (const float*)d_in[3];
    const float* bq = (const float*)d_in[4];
    const float* Wk = (const float*)d_in[5];
    const float* bk = (const float*)d_in[6];
    const float* Wv = (const float*)d_in[7];
    const float* bv = (const float*)d_in[8];
    const float* Wo = (const float*)d_in[9];
    const float* bo = (const float*)d_in[10];

    float* out  = (float*)d_out;               // [b,n,c,d]
    float* attn = out + OUT_OFF_ATTN;          // [b,c,n,m]

    void *pqkv, *pc, *ps, *pw;
    cudaGetSymbolAddress(&pqkv, g_qkv);
    cudaGetSymbolAddress(&pc, g_ctx);
    cudaGetSymbolAddress(&ps, g_sc);
    cudaGetSymbolAddress(&pw, g_wt);
    __half* qkv = (__half*)pqkv;
    __half* ctx = (__half*)pc;
    __half* sc  = (__half*)ps;
    __half* wt  = (__half*)pw;

    cudaFuncSetAttribute(gemm_mma<0>, cudaFuncAttributeMaxDynamicSharedMemorySize, SMEM_BYTES);
    cudaFuncSetAttribute(gemm_mma<2>, cudaFuncAttributeMaxDynamicSharedMemorySize, SMEM_BYTES);
    cudaFuncSetAttribute(gemm_mma<3>, cudaFuncAttributeMaxDynamicSharedMemorySize, SMEM_BYTES);
    cudaFuncSetAttribute(gemm_mma<4>, cudaFuncAttributeMaxDynamicSharedMemorySize, SMEM_BYTES);

    P3 none = {};

    // transpose + convert all four weights in one launch
    W4 ws; ws.w[0] = Wq; ws.w[1] = Wk; ws.w[2] = Wv; ws.w[3] = Wo;
    prep_w_kernel<<<dim3(16, 16, 4), 256>>>(ws, wt);

    // q/k/v projections fused into one launch (z picks input/W/bias/out)
    P3 pp;
    pp.a[0] = q;  pp.a[1] = k;  pp.a[2] = v;
    pp.b[0] = bq; pp.b[1] = bk; pp.b[2] = bv;
    gemm_mma<0><<<dim3(2, 512, 3), NTHR, SMEM_BYTES>>>(nullptr, wt, nullptr, qkv, pp);

    __half* qp = qkv;
    __half* kp = qkv + QKV_SPAN;
    __half* vp = qkv + 2*QKV_SPAN;

    // scores: per z, M=N=2048, K=512, fp16 out to g_sc
    gemm_mma<2><<<dim3(8, 16, BCN), NTHR, SMEM_BYTES>>>(qp, kp, nullptr, sc, none);

    // softmax: fp16 in -> fp32 attn (streaming) + fp16 normalized in place
    softmax_kernel<<<BCN * NSEQ / 8, 256>>>(sc, attn);

    // AV: per z, M=2048, N=512, K=2048
    gemm_mma<3><<<dim3(2, 16, BCN), NTHR, SMEM_BYTES>>>(sc, vp, nullptr, ctx, none);

    // out projection
    gemm_mma<4><<<dim3(2, 512, 1), NTHR, SMEM_BYTES>>>(ctx, wt + 3*(size_t)DM*DM, bo, out, none);
}